// round 1
// baseline (speedup 1.0000x reference)
#include <cuda_runtime.h>

// Kalman filter + RTS smoother, T = 4,194,304.
// Strategy: chunked serial scans with contraction warm-up halos.
//   Pass 1: variance reduction (r, q_base, p0 derived from data).
//   Pass 2: forward filter, chunk-per-thread (L=256) with H=256 warm-up.
//           Stores m_filt[t] and J[t] = P_f[t] / (P_f[t] + q[t+1]).
//   Pass 3: backward smoother, chunk-per-thread (L=512) with H=320 warm-up.
//           ms[t] = (1-J)*m_f[t] + J*ms[t+1], written to d_out.

#define MAX_T 4194304
#define RED_BLOCKS 512
#define RED_THREADS 256

__device__ float  g_mf[MAX_T];
__device__ float  g_J[MAX_T];
__device__ double g_psum[RED_BLOCKS];
__device__ double g_psumsq[RED_BLOCKS];
__device__ float  g_params[3];   // q_base, r, p0

// ---------------------------------------------------------------------------
// Pass 1a: per-block partial sums (sum, sumsq) of values
// ---------------------------------------------------------------------------
__global__ void reduce_kernel(const float* __restrict__ vals, int T) {
    float s = 0.f, s2 = 0.f;
    int idx    = blockIdx.x * blockDim.x + threadIdx.x;
    int stride = gridDim.x * blockDim.x;
    int n4 = T >> 2;
    const float4* v4 = (const float4*)vals;
    for (int i = idx; i < n4; i += stride) {
        float4 v = v4[i];
        s  += v.x + v.y + v.z + v.w;
        s2 += v.x * v.x + v.y * v.y + v.z * v.z + v.w * v.w;
    }
    if (idx == 0) {  // tail (T % 4), deterministic single-thread
        for (int i = T & ~3; i < T; i++) {
            float v = vals[i];
            s += v; s2 += v * v;
        }
    }
    double ds = (double)s, ds2 = (double)s2;
    for (int off = 16; off > 0; off >>= 1) {
        ds  += __shfl_down_sync(0xffffffffu, ds,  off);
        ds2 += __shfl_down_sync(0xffffffffu, ds2, off);
    }
    __shared__ double sh_s[RED_THREADS / 32], sh_s2[RED_THREADS / 32];
    int lane = threadIdx.x & 31, wid = threadIdx.x >> 5;
    if (lane == 0) { sh_s[wid] = ds; sh_s2[wid] = ds2; }
    __syncthreads();
    if (threadIdx.x == 0) {
        double ts = 0.0, ts2 = 0.0;
        for (int i = 0; i < RED_THREADS / 32; i++) { ts += sh_s[i]; ts2 += sh_s2[i]; }
        g_psum[blockIdx.x]   = ts;
        g_psumsq[blockIdx.x] = ts2;
    }
}

// ---------------------------------------------------------------------------
// Pass 1b: final reduce + derive (q_base, r, p0)
// ---------------------------------------------------------------------------
__global__ void finalize_kernel(int T) {
    __shared__ double sh_s[RED_BLOCKS], sh_s2[RED_BLOCKS];
    int t = threadIdx.x;
    sh_s[t]  = g_psum[t];
    sh_s2[t] = g_psumsq[t];
    __syncthreads();
    for (int off = RED_BLOCKS / 2; off > 0; off >>= 1) {
        if (t < off) { sh_s[t] += sh_s[t + off]; sh_s2[t] += sh_s2[t + off]; }
        __syncthreads();
    }
    if (t == 0) {
        double mean = sh_s[0] / (double)T;
        double var  = sh_s2[0] / (double)T - mean * mean;
        float var_y = (float)var + 1e-6f;       // + MIN_VAR
        g_params[0] = 0.05f * var_y;            // q_base = PROCESS_VAR_SCALE * var_y
        g_params[1] = var_y + 1e-6f;            // r = OBS_VAR_SCALE*var_y + MIN_VAR
        g_params[2] = var_y + 1e-6f;            // p0
    }
}

// ---------------------------------------------------------------------------
// Pass 2: forward filter. Chunk length L=256, warm-up H=256.
// Writes g_mf[t] = m_filt[t], g_J[t] = P_f[t]/(P_f[t] + q_base*dt[t+1]).
// ---------------------------------------------------------------------------
__global__ void fwd_kernel(const float* __restrict__ times,
                           const float* __restrict__ vals, int T) {
    const float q_base = g_params[0];
    const float r      = g_params[1];
    const float p0     = g_params[2];
    const int L = 256, H = 256;
    int c   = blockIdx.x * blockDim.x + threadIdx.x;
    int nch = (T + L - 1) / L;
    if (c >= nch) return;
    int s = c * L;
    int e = min(s + L, T);
    int w = max(0, s - H);

    float prev = (w > 0) ? times[w - 1] : 0.0f;
    float4 tcur = *(const float4*)(times + w);
    float4 ycur = *(const float4*)(vals + w);
    float P = p0;        // warm-start guess (contraction -> exact within H steps)
    float m = ycur.x;    // guess = observation at warm start; exact for w==0

    for (int g = w; g < e; g += 4) {
        float4 tnxt, ynxt;
        if (g + 4 < T) {
            tnxt = *(const float4*)(times + g + 4);
            ynxt = *(const float4*)(vals + g + 4);
        } else {
            tnxt = make_float4(tcur.w + 1.0f, 0.f, 0.f, 0.f);
            ynxt = make_float4(0.f, 0.f, 0.f, 0.f);
        }
        float tt[5] = {tcur.x, tcur.y, tcur.z, tcur.w, tnxt.x};
        float yy[4] = {ycur.x, ycur.y, ycur.z, ycur.w};
        float mf[4], Jv[4];
#pragma unroll
        for (int i = 0; i < 4; i++) {
            float cur = tt[i];
            float dt  = fmaxf(cur - prev, 1e-6f);
            if (g + i == 0) dt = 1.0f;          // reference: dt[0] = 1.0
            float q     = q_base * dt;
            float Ppred = P + q;
            float S     = Ppred + r;
            float K     = __fdividef(Ppred, S);
            m = fmaf(K, yy[i] - m, m);
            P = fmaf(-K, Ppred, Ppred);         // (1-K)*Ppred
            float dtn = fmaxf(tt[i + 1] - cur, 1e-6f);
            Jv[i] = __fdividef(P, fmaf(q_base, dtn, P));  // J[t]; garbage at t=T-1 (unused)
            mf[i] = m;
            prev = cur;
        }
        if (g >= s) {
            *(float4*)(g_mf + g) = make_float4(mf[0], mf[1], mf[2], mf[3]);
            *(float4*)(g_J + g)  = make_float4(Jv[0], Jv[1], Jv[2], Jv[3]);
        }
        tcur = tnxt; ycur = ynxt;
    }
}

// ---------------------------------------------------------------------------
// Pass 3: backward RTS smoother. Chunk length L=512, warm-up H=320 (to the right).
// ms[t] = (1-J[t])*m_f[t] + J[t]*ms[t+1]
// ---------------------------------------------------------------------------
__global__ void bwd_kernel(float* __restrict__ out, int T) {
    const int L = 512, H = 320;
    int c   = blockIdx.x * blockDim.x + threadIdx.x;
    int nch = (T + L - 1) / L;
    if (c >= nch) return;
    int s  = c * L;
    int e  = min(s + L, T);
    int we = min(e + H, T);

    float ms;
    // peeled top group: element we-1 initializes ms = m_f[we-1]
    {
        int g = we - 4;
        float4 mfv = *(const float4*)(g_mf + g);
        float4 Jv4 = *(const float4*)(g_J + g);
        float mfl[4] = {mfv.x, mfv.y, mfv.z, mfv.w};
        float Jl[4]  = {Jv4.x, Jv4.y, Jv4.z, Jv4.w};
        float om[4];
        ms = mfl[3];
        om[3] = ms;
#pragma unroll
        for (int i = 2; i >= 0; i--) {
            float cm = fmaf(-Jl[i], mfl[i], mfl[i]);   // (1-J)*m_f
            ms = fmaf(Jl[i], ms, cm);
            om[i] = ms;
        }
        if (g + 4 <= e)  // only when we == e (last chunk)
            *(float4*)(out + g) = make_float4(om[0], om[1], om[2], om[3]);
    }
    for (int g = we - 8; g >= s; g -= 4) {
        float4 mfv = *(const float4*)(g_mf + g);
        float4 Jv4 = *(const float4*)(g_J + g);
        float mfl[4] = {mfv.x, mfv.y, mfv.z, mfv.w};
        float Jl[4]  = {Jv4.x, Jv4.y, Jv4.z, Jv4.w};
        float om[4];
#pragma unroll
        for (int i = 3; i >= 0; i--) {
            float cm = fmaf(-Jl[i], mfl[i], mfl[i]);
            ms = fmaf(Jl[i], ms, cm);
            om[i] = ms;
        }
        if (g < e)  // skip warm-up groups [e, we)
            *(float4*)(out + g) = make_float4(om[0], om[1], om[2], om[3]);
    }
}

// ---------------------------------------------------------------------------
extern "C" void kernel_launch(void* const* d_in, const int* in_sizes, int n_in,
                              void* d_out, int out_size) {
    const float* times = (const float*)d_in[0];
    const float* vals  = (const float*)d_in[1];
    float* out = (float*)d_out;
    int T = in_sizes[0];

    reduce_kernel<<<RED_BLOCKS, RED_THREADS>>>(vals, T);
    finalize_kernel<<<1, RED_BLOCKS>>>(T);

    int nchf = (T + 255) / 256;
    fwd_kernel<<<(nchf + 127) / 128, 128>>>(times, vals, T);

    int nchb = (T + 511) / 512;
    bwd_kernel<<<(nchb + 127) / 128, 128>>>(out, T);
}